// round 16
// baseline (speedup 1.0000x reference)
#include <cuda_runtime.h>
#include <cuda_fp16.h>
#include <math.h>
#include <stdint.h>

// ---------------------------------------------------------------------------
// TransformerXL RPE via pure-fp16 mma.sync GEMMs (fp32 accumulate).
// out[b,i,j] = ( (Q+u)[b,i,:]·K[b,j,:] + A[b,i, clip(i-j)+M] ) / sqrt(D)
// Q = x@Wq^T, K = x@Wk^T, R = table@Wr^T, A = (Q+v)@R^T.
// All operands fp16, fp32 accumulate. rel_err ~4.3e-4 < 1e-3.
// Loop: CTA 128x128, warp 64x32, BK=64, 3-stage cp.async, 256 thr, 2 CTA/SM.
// R14 structure (4 launches; G1+G2+G3 fused) + NEW: the NA=1025 sliver tiles
// (G3 row 1024, G4 col 1024) are computed by cheap smem-staged GEMV CTAs
// instead of full 128x128 GEMM tiles -> 72 HMMA tiles removed, all remaining
// GEMM tiles bounds-check-free.
// ---------------------------------------------------------------------------

#define SDIV(a,b) (((a)+(b)-1)/(b))

static constexpr int STG      = 3;
static constexpr int TILE_B   = 128 * 128;        // 128 rows x 64 fp16 = 16 KB
static constexpr int STAGE_B  = 2 * TILE_B;       // Ah, Bh
static constexpr int SMEM_REQ = STG * STAGE_B;    // 96 KB
static constexpr int LDP      = 1028;             // padded ld for A (pos) matrix

// ---------------- scratch (B=4, L=2048, D=1024, 2M+1=1025) -----------------
__device__ __align__(1024) __half g_xh [8192u*1024u];
__device__ __align__(1024) __half g_wqh[1024u*1024u];
__device__ __align__(1024) __half g_wkh[1024u*1024u];
__device__ __align__(1024) __half g_wrh[1024u*1024u];
__device__ __align__(1024) __half g_tbh[1025u*1024u];
__device__ __align__(1024) __half g_quh[8192u*1024u];
__device__ __align__(1024) __half g_qvh[8192u*1024u];
__device__ __align__(1024) __half g_kh [8192u*1024u];
__device__ __align__(1024) __half g_rh [1025u*1024u];
__device__ __align__(1024) float  g_A  [8192u*(unsigned)LDP];

// ---------------------------- PTX helpers ----------------------------------
__device__ __forceinline__ uint32_t smem_u32(const void* p) {
    uint32_t a;
    asm("{ .reg .u64 t; cvta.to.shared.u64 t, %1; cvt.u32.u64 %0, t; }" : "=r"(a) : "l"(p));
    return a;
}
#define CP_ASYNC16(dst, src, pbytes) \
    asm volatile("cp.async.cg.shared.global [%0], [%1], 16, %2;" \
                 :: "r"(dst), "l"(src), "r"(pbytes))
#define CP_COMMIT() asm volatile("cp.async.commit_group;" ::: "memory")
#define CP_WAIT1()  asm volatile("cp.async.wait_group 1;"  ::: "memory")

#define LDSM_X4(r0,r1,r2,r3,a) \
    asm volatile("ldmatrix.sync.aligned.m8n8.x4.shared.b16 {%0,%1,%2,%3}, [%4];" \
                 : "=r"(r0), "=r"(r1), "=r"(r2), "=r"(r3) : "r"(a))
#define LDSM_X2(r0,r1,a) \
    asm volatile("ldmatrix.sync.aligned.m8n8.x2.shared.b16 {%0,%1}, [%2];" \
                 : "=r"(r0), "=r"(r1) : "r"(a))
#define MMA16816(c, a, b) \
    asm volatile("mma.sync.aligned.m16n8k16.row.col.f32.f16.f16.f32 " \
                 "{%0,%1,%2,%3}, {%4,%5,%6,%7}, {%8,%9}, {%0,%1,%2,%3};" \
                 : "+f"((c)[0]), "+f"((c)[1]), "+f"((c)[2]), "+f"((c)[3]) \
                 : "r"((a)[0]), "r"((a)[1]), "r"((a)[2]), "r"((a)[3]), \
                   "r"((b)[0]), "r"((b)[1]))

// ------------------- fused split kernel (one launch, 5 segments) ------------
__global__ void split5(const float* __restrict__ i0, const float* __restrict__ i1,
                       const float* __restrict__ i2, const float* __restrict__ i3,
                       const float* __restrict__ i4,
                       __half* __restrict__ h0, __half* __restrict__ h1,
                       __half* __restrict__ h2, __half* __restrict__ h3,
                       __half* __restrict__ h4,
                       int p0, int p1, int p2, int p3)
{
    int b = blockIdx.x;
    const float* in; __half* hi;
    if      (b < p0) { in = i0; hi = h0; }
    else if (b < p1) { in = i1; hi = h1; b -= p0; }
    else if (b < p2) { in = i2; hi = h2; b -= p1; }
    else if (b < p3) { in = i3; hi = h3; b -= p2; }
    else             { in = i4; hi = h4; b -= p3; }

    const int i = b * blockDim.x + threadIdx.x;
    float4 v = reinterpret_cast<const float4*>(in)[i];
    reinterpret_cast<__half2*>(hi)[i*2+0] =
        __halves2half2(__float2half_rn(v.x), __float2half_rn(v.y));
    reinterpret_cast<__half2*>(hi)[i*2+1] =
        __halves2half2(__float2half_rn(v.z), __float2half_rn(v.w));
}

// ---------------------- tile loader (cp.async, swizzled) --------------------
// Tile: 128 rows x 64 fp16 (128 B rows). Chunk c (16 B) of row r stored at
// r*128 + ((c ^ (r&7))*16)  -> conflict-free for both cp.async and ldmatrix.
__device__ __forceinline__ void load_tile(uint32_t dst, const __half* g,
                                          int row0, int k0, int ld, int tid) {
#pragma unroll
    for (int i = 0; i < 4; i++) {
        const int idx = tid + i * 256;
        const int r = idx >> 3, c = idx & 7;
        const __half* src = g + (size_t)(row0 + r) * ld + k0 + c * 8;
        const uint32_t d = dst + r * 128 + (((c ^ (r & 7))) << 4);
        CP_ASYNC16(d, src, 16);
    }
}

// --------------------------- shared GEMM mainloop ---------------------------
// acc[4][4][4] = Ah(128xK) * Bh(128xK)^T for this CTA tile. Proven pipeline:
// 3-stage cp.async, BK=64, swizzled ldmatrix, fp32-accum fp16 MMA.
__device__ __forceinline__ void gemm_core(
    uint32_t sb, const __half* __restrict__ gAh, const __half* __restrict__ gBh,
    int rA, int rB, int ld, int nk,
    int tid, int lane, int wid, float acc[4][4][4])
{
    const int wm = wid >> 2, wn = wid & 3;

    auto load_stage = [&](int s, int t) {
        const uint32_t base = sb + s * STAGE_B;
        const int k0 = t * 64;
        load_tile(base,          gAh, rA, k0, ld, tid);
        load_tile(base + TILE_B, gBh, rB, k0, ld, tid);
    };

    load_stage(0, 0); CP_COMMIT();
    load_stage(1, 1); CP_COMMIT();

    const int a_row = wm * 64 + (lane & 15);          // + mi*16
    const int a_cc  = lane >> 4;                      // + ks*2
    const int b_row = wn * 32 + (lane & 7);           // + ni*8
    const int b_cc  = (lane >> 3) & 1;                // + ks*2

    for (int t = 0; t < nk; t++) {
        CP_WAIT1();
        __syncthreads();
        if (t + 2 < nk) load_stage((t + 2) % STG, t + 2);
        CP_COMMIT();

        const uint32_t base = sb + (t % STG) * STAGE_B;
        const uint32_t sAh = base, sBh = base + TILE_B;

#pragma unroll
        for (int ks = 0; ks < 4; ks++) {
            uint32_t fAh[4][4], fBh[4][2];
#pragma unroll
            for (int mi = 0; mi < 4; mi++) {
                const int row = a_row + mi * 16;
                const int cc = ks * 2 + a_cc;
                const uint32_t off = row * 128 + (((cc ^ (row & 7))) << 4);
                LDSM_X4(fAh[mi][0], fAh[mi][1], fAh[mi][2], fAh[mi][3], sAh + off);
            }
#pragma unroll
            for (int ni = 0; ni < 4; ni++) {
                const int row = b_row + ni * 8;
                const int cc = ks * 2 + b_cc;
                const uint32_t off = row * 128 + (((cc ^ (row & 7))) << 4);
                LDSM_X2(fBh[ni][0], fBh[ni][1], sBh + off);
            }
#pragma unroll
            for (int mi = 0; mi < 4; mi++)
#pragma unroll
                for (int ni = 0; ni < 4; ni++) MMA16816(acc[mi][ni], fAh[mi], fBh[ni]);
        }
    }
}

// ---------------------- GEMV helper (sliver rows/cols) ----------------------
// out1 = dot( vec (staged in smem, D halves), mat[row j] ), 2 threads per j.
__device__ __forceinline__ float gemv_dot(const __half* sm, const __half* matrow,
                                          int D, int tid) {
    const int hof = (tid & 1) * (D >> 1);
    const __half2* a2 = reinterpret_cast<const __half2*>(matrow + hof);
    const __half2* t2 = reinterpret_cast<const __half2*>(sm + hof);
    float s = 0.f;
    const int n2 = D >> 2;
#pragma unroll 4
    for (int d = 0; d < n2; d++) {
        const float2 av = __half22float2(a2[d]);
        const float2 tv = __half22float2(t2[d]);
        s = fmaf(av.x, tv.x, s);
        s = fmaf(av.y, tv.y, s);
    }
    s += __shfl_xor_sync(0xffffffffu, s, 1);
    return s;
}

// -------------------- fused G1+G2+G3 kernel (one launch) --------------------
// seg0 [0,g1):     Qu/Qv = x@Wq^T + u/v   (rows 0..BL)
// seg1 [g1,g12):   K = x@Wk^T
// seg2 [g12,g123): R rows 0..1023 = table@Wr^T  (full tiles, no bounds)
// seg3 [g123,..):  R row 1024 via GEMV (8 CTAs, 128 cols each)
__global__ __launch_bounds__(256, 2)
void tc_gemm_f123(const __half* __restrict__ xh,  const __half* __restrict__ wqh,
                  const __half* __restrict__ wkh,
                  const __half* __restrict__ tbh, const __half* __restrict__ wrh,
                  __half* __restrict__ quh, __half* __restrict__ qvh,
                  __half* __restrict__ kh,  __half* __restrict__ rh,
                  const float* __restrict__ u, const float* __restrict__ v,
                  int D, int NA, int nk, int g1, int g12, int g123)
{
    extern __shared__ __align__(128) char smem_raw[];
    const uint32_t sb = smem_u32(smem_raw);
    const int tid = threadIdx.x, lane = tid & 31, wid = tid >> 5;

    int b = blockIdx.x;

    if (b >= g123) {                 // ---- seg3: R row 1024 GEMV ----
        b -= g123;
        __half* sm = reinterpret_cast<__half*>(smem_raw);
        const __half* t1024 = tbh + (size_t)(NA - 1) * D;
        for (int i = tid; i < D; i += 256) sm[i] = t1024[i];
        __syncthreads();
        const int j = b * 128 + (tid >> 1);
        const float s = gemv_dot(sm, wrh + (size_t)j * D, D, tid);
        if ((tid & 1) == 0) rh[(size_t)(NA - 1) * D + j] = __float2half_rn(s);
        return;
    }

    int seg; const __half *gA, *gB;
    if (b < g1)       { seg = 0; gA = xh;  gB = wqh; }
    else if (b < g12) { seg = 1; gA = xh;  gB = wkh; b -= g1; }
    else              { seg = 2; gA = tbh; gB = wrh; b -= g12; }

    const int nx = D >> 7;                       // 8 column tiles (N = D)
    const int bn = (b % nx) * 128;
    const int bm = (b / nx) * 128;

    float acc[4][4][4];
#pragma unroll
    for (int mi = 0; mi < 4; mi++)
#pragma unroll
        for (int ni = 0; ni < 4; ni++)
#pragma unroll
            for (int q = 0; q < 4; q++) acc[mi][ni][q] = 0.f;

    gemm_core(sb, gA, gB, bm, bn, D, nk, tid, lane, wid, acc);

    const int wm = wid >> 2, wn = wid & 3;
    const int lr = lane >> 2, lc = (lane & 3) * 2;

#pragma unroll
    for (int mi = 0; mi < 4; mi++) {
#pragma unroll
        for (int ni = 0; ni < 4; ni++) {
            const float* cc = acc[mi][ni];
            const int n = bn + wn * 32 + ni * 8 + lc;
#pragma unroll
            for (int h = 0; h < 2; h++) {
                const int m = bm + wm * 64 + mi * 16 + lr + h * 8;
                const float v0 = cc[h * 2 + 0], v1 = cc[h * 2 + 1];
                if (seg == 0) {
                    const size_t o = (size_t)m * D + n;
                    *reinterpret_cast<__half2*>(quh + o) =
                        __halves2half2(__float2half_rn(v0 + u[n]),
                                       __float2half_rn(v1 + u[n + 1]));
                    *reinterpret_cast<__half2*>(qvh + o) =
                        __halves2half2(__float2half_rn(v0 + v[n]),
                                       __float2half_rn(v1 + v[n + 1]));
                } else {
                    __half* C = (seg == 1) ? kh : rh;
                    *reinterpret_cast<__half2*>(C + (size_t)m * D + n) =
                        __halves2half2(__float2half_rn(v0), __float2half_rn(v1));
                }
            }
        }
    }
}

// ------------------------------ GEMM kernel ---------------------------------
// MODE 0: A = Qv@R^T, fp32 store (ldc=LDP). blockIdx.x==8 plane computes the
//         sliver column A[:,1024] via GEMV (R row 1024 staged in smem).
// MODE 2: out = (acc + Apos[m, clip(m-n)+mr]) * scale  (batched z)
template <int MODE>
__global__ __launch_bounds__(256, 2)
void tc_gemm(const __half* __restrict__ gAh, const __half* __restrict__ gBh,
             void* C0,
             const float* __restrict__ Apos,
             int ld, int ldc, int rowOffA, int rowOffB,
             long long sC, long long sP, int maxrel, int ldp, float scale, int nk)
{
    extern __shared__ __align__(128) char smem_raw[];
    const uint32_t sb = smem_u32(smem_raw);
    const int tid = threadIdx.x, lane = tid & 31, wid = tid >> 5;

    if (MODE == 0 && blockIdx.x == 8) {   // ---- A[:,1024] GEMV plane ----
        __half* sm = reinterpret_cast<__half*>(smem_raw);
        const __half* r1024 = gBh + (size_t)1024 * ld;    // R row 1024
        for (int i = tid; i < ld; i += 256) sm[i] = r1024[i];
        __syncthreads();
        const int m = blockIdx.y * 128 + (tid >> 1);
        const float s = gemv_dot(sm, gAh + (size_t)m * ld, ld, tid);
        if ((tid & 1) == 0) ((float*)C0)[(size_t)m * ldc + 1024] = s;
        return;
    }

    const int bm = blockIdx.y * 128, bn = blockIdx.x * 128, bz = blockIdx.z;
    const int rA = bz * rowOffA + bm;
    const int rB = bz * rowOffB + bn;

    float acc[4][4][4];
#pragma unroll
    for (int mi = 0; mi < 4; mi++)
#pragma unroll
        for (int ni = 0; ni < 4; ni++)
#pragma unroll
            for (int q = 0; q < 4; q++) acc[mi][ni][q] = 0.f;

    gemm_core(sb, gAh, gBh, rA, rB, ld, nk, tid, lane, wid, acc);

    const int wm = wid >> 2, wn = wid & 3;
    const int lr = lane >> 2, lc = (lane & 3) * 2;

#pragma unroll
    for (int mi = 0; mi < 4; mi++) {
#pragma unroll
        for (int ni = 0; ni < 4; ni++) {
            const float* cc = acc[mi][ni];
            const int n = bn + wn * 32 + ni * 8 + lc;
#pragma unroll
            for (int h = 0; h < 2; h++) {
                const int m = bm + wm * 64 + mi * 16 + lr + h * 8;
                const float v0 = cc[h * 2 + 0], v1 = cc[h * 2 + 1];
                if (MODE == 0) {
                    *reinterpret_cast<float2*>((float*)C0 + (size_t)m * ldc + n) =
                        make_float2(v0, v1);
                } else { // MODE 2
                    const float* Ap = Apos + (size_t)bz * sP + (size_t)m * ldp + maxrel;
                    float* Ob = (float*)C0 + (size_t)bz * sC + (size_t)m * ldc;
                    int r0 = m - n;
                    r0 = r0 > maxrel ? maxrel : (r0 < -maxrel ? -maxrel : r0);
                    int r1 = m - (n + 1);
                    r1 = r1 > maxrel ? maxrel : (r1 < -maxrel ? -maxrel : r1);
                    *reinterpret_cast<float2*>(Ob + n) =
                        make_float2((v0 + Ap[r0]) * scale, (v1 + Ap[r1]) * scale);
                }
            }
        }
    }
}

// ------------------------------- host side ----------------------------------
extern "C" void kernel_launch(void* const* d_in, const int* in_sizes, int n_in,
                              void* d_out, int out_size)
{
    const float* x     = (const float*)d_in[0];
    const float* Wq    = (const float*)d_in[1];
    const float* Wk    = (const float*)d_in[2];
    const float* Wr    = (const float*)d_in[3];
    const float* u     = (const float*)d_in[4];
    const float* v     = (const float*)d_in[5];
    const float* table = (const float*)d_in[6];
    float* out = (float*)d_out;

    const int  D    = in_sizes[4];                    // 1024
    const int  NA   = in_sizes[6] / D;                // 1025
    const int  MREL = (NA - 1) / 2;                   // 512
    const long long BL = (long long)in_sizes[0] / D;  // 8192
    const int  L  = (int)((long long)out_size / BL);  // 2048
    const int  Bn = (int)(BL / L);                    // 4
    const int  nk = D / 64;                           // 16
    const float scale = 1.f / sqrtf((float)D);

    void *xh,*wqh,*wkh,*wrh,*tbh;
    void *quh,*qvh,*kh,*rh,*Aa;
    cudaGetSymbolAddress(&xh,  g_xh);
    cudaGetSymbolAddress(&wqh, g_wqh);
    cudaGetSymbolAddress(&wkh, g_wkh);
    cudaGetSymbolAddress(&wrh, g_wrh);
    cudaGetSymbolAddress(&tbh, g_tbh);
    cudaGetSymbolAddress(&quh, g_quh);
    cudaGetSymbolAddress(&qvh, g_qvh);
    cudaGetSymbolAddress(&kh,  g_kh);
    cudaGetSymbolAddress(&rh,  g_rh);
    cudaGetSymbolAddress(&Aa,  g_A);

    static bool attr_done = false;
    if (!attr_done) {
        cudaFuncSetAttribute(tc_gemm_f123, cudaFuncAttributeMaxDynamicSharedMemorySize, SMEM_REQ);
        cudaFuncSetAttribute(tc_gemm<0>,   cudaFuncAttributeMaxDynamicSharedMemorySize, SMEM_REQ);
        cudaFuncSetAttribute(tc_gemm<2>,   cudaFuncAttributeMaxDynamicSharedMemorySize, SMEM_REQ);
        attr_done = true;
    }

    // ---- fused split: one launch, fp16-round x, Wq, Wk, Wr, table ----
    {
        const int T = 256;
        const int bx = (int)(BL * D / 4) / T;   // 8192
        const int bw = (D * D / 4) / T;         // 1024
        const int bt = (NA * D / 4) / T;        // 1025
        const int p0 = bx, p1 = p0 + bw, p2 = p1 + bw, p3 = p2 + bw;
        split5<<<p3 + bt, T>>>(x, Wq, Wk, Wr, table,
            (__half*)xh, (__half*)wqh, (__half*)wkh, (__half*)wrh, (__half*)tbh,
            p0, p1, p2, p3);
    }

    const dim3 blk(256);

    // ---- fused G1+G2+G3(+R-sliver GEMV): one launch (1096 CTAs) ----
    {
        const int nx  = D / 128;                      // 8
        const int g1  = nx * (int)(BL / 128);         // 512
        const int g12 = g1 + g1;                      // 1024
        const int g123 = g12 + nx * nx;               // +64 full R tiles = 1088
        const int gemv = nx;                          // 8 GEMV CTAs (R row 1024)
        tc_gemm_f123<<<g123 + gemv, blk, SMEM_REQ>>>(
            (const __half*)xh, (const __half*)wqh, (const __half*)wkh,
            (const __half*)tbh, (const __half*)wrh,
            (__half*)quh, (__half*)qvh, (__half*)kh, (__half*)rh,
            u, v, D, NA, nk, g1, g12, g123);
    }

    // 4) A = Qv@R^T -> fp32, ldc=LDP. x-plane 8 = GEMV for A[:,1024].
    tc_gemm<0><<<dim3(9, (int)(BL/128), 1), blk, SMEM_REQ>>>(
        (const __half*)qvh, (const __half*)rh,
        Aa, nullptr,
        D, LDP, 0, 0, 0, 0, 0, 0, 0.f, nk);

    // 5) out = (Qu@K^T + gather(A)) * scale, batched over B
    tc_gemm<2><<<dim3(L/128, L/128, Bn), blk, SMEM_REQ>>>(
        (const __half*)quh, (const __half*)kh,
        out, (const float*)Aa,
        D, L, L, L,
        (long long)L * L, (long long)L * LDP, MREL, LDP, scale, nk);
}

// round 17
// speedup vs baseline: 1.1872x; 1.1872x over previous
#include <cuda_runtime.h>
#include <cuda_fp16.h>
#include <math.h>
#include <stdint.h>

// ---------------------------------------------------------------------------
// TransformerXL RPE via pure-fp16 mma.sync GEMMs (fp32 accumulate).
// out[b,i,j] = ( (Q+u)[b,i,:]·K[b,j,:] + A[b,i, clip(i-j)+M] ) / sqrt(D)
// Q = x@Wq^T, K = x@Wk^T, R = table@Wr^T, A = (Q+v)@R^T.
// All operands fp16, fp32 accumulate. rel_err ~4.6e-4 < 1e-3.
// Loop: CTA 128x128, warp 64x32, BK=64, 3-stage cp.async, 256 thr, 2 CTA/SM.
// R14 structure (proven 303us): 4 launches, G1+G2+G3 fused via segment decode.
// NEW vs R14: intermediate A matrix stored fp16 (halves G4 store + G5 gather
// bytes through the 61%-busy L1 path).
// ---------------------------------------------------------------------------

#define SDIV(a,b) (((a)+(b)-1)/(b))

static constexpr int STG      = 3;
static constexpr int TILE_B   = 128 * 128;        // 128 rows x 64 fp16 = 16 KB
static constexpr int STAGE_B  = 2 * TILE_B;       // Ah, Bh
static constexpr int SMEM_REQ = STG * STAGE_B;    // 96 KB
static constexpr int LDP      = 1032;             // padded ld for A (pos) matrix

// ---------------- scratch (B=4, L=2048, D=1024, 2M+1=1025) -----------------
__device__ __align__(1024) __half g_xh [8192u*1024u];
__device__ __align__(1024) __half g_wqh[1024u*1024u];
__device__ __align__(1024) __half g_wkh[1024u*1024u];
__device__ __align__(1024) __half g_wrh[1024u*1024u];
__device__ __align__(1024) __half g_tbh[1025u*1024u];
__device__ __align__(1024) __half g_quh[8192u*1024u];
__device__ __align__(1024) __half g_qvh[8192u*1024u];
__device__ __align__(1024) __half g_kh [8192u*1024u];
__device__ __align__(1024) __half g_rh [1025u*1024u];
__device__ __align__(1024) __half g_A  [8192u*(unsigned)LDP];

// ---------------------------- PTX helpers ----------------------------------
__device__ __forceinline__ uint32_t smem_u32(const void* p) {
    uint32_t a;
    asm("{ .reg .u64 t; cvta.to.shared.u64 t, %1; cvt.u32.u64 %0, t; }" : "=r"(a) : "l"(p));
    return a;
}
#define CP_ASYNC16(dst, src, pbytes) \
    asm volatile("cp.async.cg.shared.global [%0], [%1], 16, %2;" \
                 :: "r"(dst), "l"(src), "r"(pbytes))
#define CP_COMMIT() asm volatile("cp.async.commit_group;" ::: "memory")
#define CP_WAIT1()  asm volatile("cp.async.wait_group 1;"  ::: "memory")

#define LDSM_X4(r0,r1,r2,r3,a) \
    asm volatile("ldmatrix.sync.aligned.m8n8.x4.shared.b16 {%0,%1,%2,%3}, [%4];" \
                 : "=r"(r0), "=r"(r1), "=r"(r2), "=r"(r3) : "r"(a))
#define LDSM_X2(r0,r1,a) \
    asm volatile("ldmatrix.sync.aligned.m8n8.x2.shared.b16 {%0,%1}, [%2];" \
                 : "=r"(r0), "=r"(r1) : "r"(a))
#define MMA16816(c, a, b) \
    asm volatile("mma.sync.aligned.m16n8k16.row.col.f32.f16.f16.f32 " \
                 "{%0,%1,%2,%3}, {%4,%5,%6,%7}, {%8,%9}, {%0,%1,%2,%3};" \
                 : "+f"((c)[0]), "+f"((c)[1]), "+f"((c)[2]), "+f"((c)[3]) \
                 : "r"((a)[0]), "r"((a)[1]), "r"((a)[2]), "r"((a)[3]), \
                   "r"((b)[0]), "r"((b)[1]))

// ------------------- fused split kernel (one launch, 5 segments) ------------
__global__ void split5(const float* __restrict__ i0, const float* __restrict__ i1,
                       const float* __restrict__ i2, const float* __restrict__ i3,
                       const float* __restrict__ i4,
                       __half* __restrict__ h0, __half* __restrict__ h1,
                       __half* __restrict__ h2, __half* __restrict__ h3,
                       __half* __restrict__ h4,
                       int p0, int p1, int p2, int p3)
{
    int b = blockIdx.x;
    const float* in; __half* hi;
    if      (b < p0) { in = i0; hi = h0; }
    else if (b < p1) { in = i1; hi = h1; b -= p0; }
    else if (b < p2) { in = i2; hi = h2; b -= p1; }
    else if (b < p3) { in = i3; hi = h3; b -= p2; }
    else             { in = i4; hi = h4; b -= p3; }

    const int i = b * blockDim.x + threadIdx.x;
    float4 v = reinterpret_cast<const float4*>(in)[i];
    reinterpret_cast<__half2*>(hi)[i*2+0] =
        __halves2half2(__float2half_rn(v.x), __float2half_rn(v.y));
    reinterpret_cast<__half2*>(hi)[i*2+1] =
        __halves2half2(__float2half_rn(v.z), __float2half_rn(v.w));
}

// ---------------------- tile loader (cp.async, swizzled) --------------------
// Tile: 128 rows x 64 fp16 (128 B rows). Chunk c (16 B) of row r stored at
// r*128 + ((c ^ (r&7))*16)  -> conflict-free for both cp.async and ldmatrix.
__device__ __forceinline__ void load_tile(uint32_t dst, const __half* g,
                                          int row0, int rows_max, int k0, int ld,
                                          int tid, bool bchk) {
#pragma unroll
    for (int i = 0; i < 4; i++) {
        const int idx = tid + i * 256;
        const int r = idx >> 3, c = idx & 7;
        int row = row0 + r;
        unsigned p = 16;
        if (bchk && row >= rows_max) { p = 0; row = 0; }
        const __half* src = g + (size_t)row * ld + k0 + c * 8;
        const uint32_t d = dst + r * 128 + (((c ^ (r & 7))) << 4);
        CP_ASYNC16(d, src, p);
    }
}

// --------------------------- shared GEMM mainloop ---------------------------
__device__ __forceinline__ void gemm_core(
    uint32_t sb, const __half* __restrict__ gAh, const __half* __restrict__ gBh,
    int rA, int rB, int M, int N, int ld, int nk, bool bchk,
    int tid, int lane, int wid, float acc[4][4][4])
{
    const int wm = wid >> 2, wn = wid & 3;

    auto load_stage = [&](int s, int t) {
        const uint32_t base = sb + s * STAGE_B;
        const int k0 = t * 64;
        load_tile(base,          gAh, rA, M, k0, ld, tid, bchk);
        load_tile(base + TILE_B, gBh, rB, N, k0, ld, tid, bchk);
    };

    load_stage(0, 0); CP_COMMIT();
    load_stage(1, 1); CP_COMMIT();

    const int a_row = wm * 64 + (lane & 15);          // + mi*16
    const int a_cc  = lane >> 4;                      // + ks*2
    const int b_row = wn * 32 + (lane & 7);           // + ni*8
    const int b_cc  = (lane >> 3) & 1;                // + ks*2

    for (int t = 0; t < nk; t++) {
        CP_WAIT1();
        __syncthreads();
        if (t + 2 < nk) load_stage((t + 2) % STG, t + 2);
        CP_COMMIT();

        const uint32_t base = sb + (t % STG) * STAGE_B;
        const uint32_t sAh = base, sBh = base + TILE_B;

#pragma unroll
        for (int ks = 0; ks < 4; ks++) {
            uint32_t fAh[4][4], fBh[4][2];
#pragma unroll
            for (int mi = 0; mi < 4; mi++) {
                const int row = a_row + mi * 16;
                const int cc = ks * 2 + a_cc;
                const uint32_t off = row * 128 + (((cc ^ (row & 7))) << 4);
                LDSM_X4(fAh[mi][0], fAh[mi][1], fAh[mi][2], fAh[mi][3], sAh + off);
            }
#pragma unroll
            for (int ni = 0; ni < 4; ni++) {
                const int row = b_row + ni * 8;
                const int cc = ks * 2 + b_cc;
                const uint32_t off = row * 128 + (((cc ^ (row & 7))) << 4);
                LDSM_X2(fBh[ni][0], fBh[ni][1], sBh + off);
            }
#pragma unroll
            for (int mi = 0; mi < 4; mi++)
#pragma unroll
                for (int ni = 0; ni < 4; ni++) MMA16816(acc[mi][ni], fAh[mi], fBh[ni]);
        }
    }
}

// -------------------- fused G1+G2+G3 kernel (one launch) --------------------
// seg0 [0,g1):       Qu/Qv = x@Wq^T + u/v   (M=BL)
// seg1 [g1,g1+g2):   K = x@Wk^T             (M=BL)
// seg2 [g1+g2,...):  R = table@Wr^T         (M=NA, bounds-checked)
__global__ __launch_bounds__(256, 2)
void tc_gemm_f123(const __half* __restrict__ xh,  const __half* __restrict__ wqh,
                  const __half* __restrict__ wkh,
                  const __half* __restrict__ tbh, const __half* __restrict__ wrh,
                  __half* __restrict__ quh, __half* __restrict__ qvh,
                  __half* __restrict__ kh,  __half* __restrict__ rh,
                  const float* __restrict__ u, const float* __restrict__ v,
                  int BLi, int NA, int D, int nk, int g1, int g12)
{
    extern __shared__ __align__(128) char smem_raw[];
    const uint32_t sb = smem_u32(smem_raw);
    const int tid = threadIdx.x, lane = tid & 31, wid = tid >> 5;

    int b = blockIdx.x;
    int seg; const __half *gA, *gB; int M;
    if (b < g1)       { seg = 0; gA = xh;  gB = wqh; M = BLi; }
    else if (b < g12) { seg = 1; gA = xh;  gB = wkh; M = BLi; b -= g1; }
    else              { seg = 2; gA = tbh; gB = wrh; M = NA;  b -= g12; }

    const int nx = D >> 7;                       // 8 column tiles (N = D)
    const int bn = (b % nx) * 128;
    const int bm = (b / nx) * 128;
    const bool bchk = (seg == 2);

    float acc[4][4][4];
#pragma unroll
    for (int mi = 0; mi < 4; mi++)
#pragma unroll
        for (int ni = 0; ni < 4; ni++)
#pragma unroll
            for (int q = 0; q < 4; q++) acc[mi][ni][q] = 0.f;

    gemm_core(sb, gA, gB, bm, bn, M, D, D, nk, bchk, tid, lane, wid, acc);

    const int wm = wid >> 2, wn = wid & 3;
    const int lr = lane >> 2, lc = (lane & 3) * 2;

#pragma unroll
    for (int mi = 0; mi < 4; mi++) {
#pragma unroll
        for (int ni = 0; ni < 4; ni++) {
            const float* cc = acc[mi][ni];
            const int n = bn + wn * 32 + ni * 8 + lc;
#pragma unroll
            for (int h = 0; h < 2; h++) {
                const int m = bm + wm * 64 + mi * 16 + lr + h * 8;
                const float v0 = cc[h * 2 + 0], v1 = cc[h * 2 + 1];
                if (seg == 0) {
                    const size_t o = (size_t)m * D + n;
                    *reinterpret_cast<__half2*>(quh + o) =
                        __halves2half2(__float2half_rn(v0 + u[n]),
                                       __float2half_rn(v1 + u[n + 1]));
                    *reinterpret_cast<__half2*>(qvh + o) =
                        __halves2half2(__float2half_rn(v0 + v[n]),
                                       __float2half_rn(v1 + v[n + 1]));
                } else {
                    if (seg == 2 && m >= M) continue;
                    __half* C = (seg == 1) ? kh : rh;
                    *reinterpret_cast<__half2*>(C + (size_t)m * D + n) =
                        __halves2half2(__float2half_rn(v0), __float2half_rn(v1));
                }
            }
        }
    }
}

// ------------------------------ GEMM kernel ---------------------------------
// MODE 0: A = Qv@R^T -> fp16 store (ldc=LDP)                 [GEMM4]
// MODE 2: out = (acc + Apos_f16[m, clip(m-n)+mr]) * scale    [GEMM5, batched]
template <int MODE, bool BCHK>
__global__ __launch_bounds__(256, 2)
void tc_gemm(const __half* __restrict__ gAh, const __half* __restrict__ gBh,
             void* C0,
             const __half* __restrict__ Apos,
             int M, int N, int ld, int ldc, int rowOffA, int rowOffB,
             long long sC, long long sP, int maxrel, int ldp, float scale, int nk)
{
    extern __shared__ __align__(128) char smem_raw[];
    const uint32_t sb = smem_u32(smem_raw);
    const int tid = threadIdx.x, lane = tid & 31, wid = tid >> 5;
    const int bm = blockIdx.y * 128, bn = blockIdx.x * 128, bz = blockIdx.z;
    const int rA = bz * rowOffA + bm;
    const int rB = bz * rowOffB + bn;

    float acc[4][4][4];
#pragma unroll
    for (int mi = 0; mi < 4; mi++)
#pragma unroll
        for (int ni = 0; ni < 4; ni++)
#pragma unroll
            for (int q = 0; q < 4; q++) acc[mi][ni][q] = 0.f;

    gemm_core(sb, gAh, gBh, rA, rB, M, N, ld, nk, BCHK, tid, lane, wid, acc);

    const int wm = wid >> 2, wn = wid & 3;
    const int lr = lane >> 2, lc = (lane & 3) * 2;

#pragma unroll
    for (int mi = 0; mi < 4; mi++) {
#pragma unroll
        for (int ni = 0; ni < 4; ni++) {
            const float* cc = acc[mi][ni];
            const int n = bn + wn * 32 + ni * 8 + lc;
#pragma unroll
            for (int h = 0; h < 2; h++) {
                const int m = bm + wm * 64 + mi * 16 + lr + h * 8;
                const float v0 = cc[h * 2 + 0], v1 = cc[h * 2 + 1];
                if (MODE == 0) {
                    if (BCHK && m >= M) continue;
                    __half* Cf = (__half*)C0;
                    if (!BCHK || n + 1 < N) {
                        *reinterpret_cast<__half2*>(Cf + (size_t)m * ldc + n) =
                            __halves2half2(__float2half_rn(v0), __float2half_rn(v1));
                    } else if (n < N) {
                        Cf[(size_t)m * ldc + n] = __float2half_rn(v0);
                    }
                } else { // MODE 2
                    const __half* Ap = Apos + (size_t)bz * sP + (size_t)m * ldp + maxrel;
                    float* Ob = (float*)C0 + (size_t)bz * sC + (size_t)m * ldc;
                    int r0 = m - n;
                    r0 = r0 > maxrel ? maxrel : (r0 < -maxrel ? -maxrel : r0);
                    int r1 = m - (n + 1);
                    r1 = r1 > maxrel ? maxrel : (r1 < -maxrel ? -maxrel : r1);
                    *reinterpret_cast<float2*>(Ob + n) =
                        make_float2((v0 + __half2float(Ap[r0])) * scale,
                                    (v1 + __half2float(Ap[r1])) * scale);
                }
            }
        }
    }
}

// ------------------------------- host side ----------------------------------
extern "C" void kernel_launch(void* const* d_in, const int* in_sizes, int n_in,
                              void* d_out, int out_size)
{
    const float* x     = (const float*)d_in[0];
    const float* Wq    = (const float*)d_in[1];
    const float* Wk    = (const float*)d_in[2];
    const float* Wr    = (const float*)d_in[3];
    const float* u     = (const float*)d_in[4];
    const float* v     = (const float*)d_in[5];
    const float* table = (const float*)d_in[6];
    float* out = (float*)d_out;

    const int  D    = in_sizes[4];                    // 1024
    const int  NA   = in_sizes[6] / D;                // 1025
    const int  MREL = (NA - 1) / 2;                   // 512
    const long long BL = (long long)in_sizes[0] / D;  // 8192
    const int  L  = (int)((long long)out_size / BL);  // 2048
    const int  Bn = (int)(BL / L);                    // 4
    const int  nk = D / 64;                           // 16
    const float scale = 1.f / sqrtf((float)D);

    void *xh,*wqh,*wkh,*wrh,*tbh;
    void *quh,*qvh,*kh,*rh,*Aa;
    cudaGetSymbolAddress(&xh,  g_xh);
    cudaGetSymbolAddress(&wqh, g_wqh);
    cudaGetSymbolAddress(&wkh, g_wkh);
    cudaGetSymbolAddress(&wrh, g_wrh);
    cudaGetSymbolAddress(&tbh, g_tbh);
    cudaGetSymbolAddress(&quh, g_quh);
    cudaGetSymbolAddress(&qvh, g_qvh);
    cudaGetSymbolAddress(&kh,  g_kh);
    cudaGetSymbolAddress(&rh,  g_rh);
    cudaGetSymbolAddress(&Aa,  g_A);

    static bool attr_done = false;
    if (!attr_done) {
        cudaFuncSetAttribute(tc_gemm_f123,     cudaFuncAttributeMaxDynamicSharedMemorySize, SMEM_REQ);
        cudaFuncSetAttribute(tc_gemm<0,true >, cudaFuncAttributeMaxDynamicSharedMemorySize, SMEM_REQ);
        cudaFuncSetAttribute(tc_gemm<2,false>, cudaFuncAttributeMaxDynamicSharedMemorySize, SMEM_REQ);
        attr_done = true;
    }

    // ---- fused split: one launch, fp16-round x, Wq, Wk, Wr, table ----
    {
        const int T = 256;
        const int bx = (int)(BL * D / 4) / T;   // 8192
        const int bw = (D * D / 4) / T;         // 1024
        const int bt = (NA * D / 4) / T;        // 1025
        const int p0 = bx, p1 = p0 + bw, p2 = p1 + bw, p3 = p2 + bw;
        split5<<<p3 + bt, T>>>(x, Wq, Wk, Wr, table,
            (__half*)xh, (__half*)wqh, (__half*)wkh, (__half*)wrh, (__half*)tbh,
            p0, p1, p2, p3);
    }

    const dim3 blk(256);

    // ---- fused G1+G2+G3: one launch (1096 CTAs) ----
    {
        const int nx = D / 128;                       // 8
        const int g1 = nx * (int)(BL / 128);          // 512
        const int g2 = g1;                            // 512
        const int g3 = nx * SDIV(NA, 128);            // 72
        tc_gemm_f123<<<g1 + g2 + g3, blk, SMEM_REQ>>>(
            (const __half*)xh, (const __half*)wqh, (const __half*)wkh,
            (const __half*)tbh, (const __half*)wrh,
            (__half*)quh, (__half*)qvh, (__half*)kh, (__half*)rh,
            u, v, (int)BL, NA, D, nk, g1, g1 + g2);
    }

    // 4) A = Qv@R^T -> fp16, ldc=LDP  (MODE 0, N bounds 1025)
    tc_gemm<0,true><<<dim3(SDIV(NA,128), (int)(BL/128), 1), blk, SMEM_REQ>>>(
        (const __half*)qvh, (const __half*)rh,
        Aa, nullptr,
        (int)BL, NA, D, LDP, 0, 0, 0, 0, 0, 0, 0.f, nk);

    // 5) out = (Qu@K^T + gather(A_f16)) * scale, batched over B  (MODE 2)
    tc_gemm<2,false><<<dim3(L/128, L/128, Bn), blk, SMEM_REQ>>>(
        (const __half*)quh, (const __half*)kh,
        out, (const __half*)Aa,
        L, L, D, L, L, L,
        (long long)L * L, (long long)L * LDP, MREL, LDP, scale, nk);
}